// round 2
// baseline (speedup 1.0000x reference)
#include <cuda_runtime.h>
#include <cstdint>

#define Bn 2
#define Cn 64
#define Hn 384
#define Wn 384
#define Gn 4
#define GCn 16
#define OMD 112   // Wom columns
#define OMS 108   // used off/mask channels
#define TILES_X (Wn/64)           // 6
#define NTILE (Bn*Hn*TILES_X)     // 4608
#define HW (Hn*Wn)

// k_sample tiling
#define TS 8
#define PATCH 12                   // TS + 2*2 halo
#define PPIX (PATCH*PATCH)         // 144
#define TXT (Wn/TS)                // 48
#define TYT (Hn/TS)                // 48
#define NTILE2 (Bn*TYT*TXT)        // 4608

__device__ __align__(16) float g_value[Bn*HW*Cn];     // [b,h,w,c]  NHWC
__device__ __align__(16) float g_offmask[Bn*HW*OMS];  // [b,h,w,108]

// ---------------------------------------------------------------------------
// Kernel 1: value = NHWC(inp) @ Wv + bv   -> g_value
// ---------------------------------------------------------------------------
__global__ __launch_bounds__(256) void k_value(const float* __restrict__ inp,
                                               const float* __restrict__ Wv,
                                               const float* __restrict__ bv) {
    __shared__ float x_s[64*64];  // [k(ch)][p(pixel)]
    __shared__ float w_s[64*64];  // [k][c]
    int t  = blockIdx.x;
    int w0 = (t % TILES_X) * 64;
    int h  = (t / TILES_X) % Hn;
    int b  = t / (TILES_X * Hn);
    int tid = threadIdx.x;

    const float* src = inp + (size_t)b*Cn*HW + (size_t)h*Wn + w0;
    #pragma unroll
    for (int i = tid; i < 4096; i += 256) {
        int c = i >> 6, p = i & 63;
        x_s[i] = src[(size_t)c*HW + p];
        w_s[i] = Wv[i];
    }
    __syncthreads();

    int ty = tid >> 4, tx = tid & 15;   // ty -> pixel group, tx -> channel group
    float acc[4][4];
    #pragma unroll
    for (int i = 0; i < 4; i++)
        #pragma unroll
        for (int j = 0; j < 4; j++) acc[i][j] = 0.f;

    const float4* x4 = (const float4*)x_s;
    const float4* w4 = (const float4*)w_s;
    #pragma unroll
    for (int k = 0; k < 64; k++) {
        float4 a  = x4[k*16 + ty];   // 4 pixels
        float4 bb = w4[k*16 + tx];   // 4 channels
        float av[4] = {a.x, a.y, a.z, a.w};
        float bw[4] = {bb.x, bb.y, bb.z, bb.w};
        #pragma unroll
        for (int i = 0; i < 4; i++)
            #pragma unroll
            for (int j = 0; j < 4; j++)
                acc[i][j] = fmaf(av[i], bw[j], acc[i][j]);
    }
    float4 bias = *(const float4*)(bv + tx*4);
    int pixbase = (b*Hn + h)*Wn + w0;
    #pragma unroll
    for (int i = 0; i < 4; i++) {
        float4 v = make_float4(acc[i][0]+bias.x, acc[i][1]+bias.y,
                               acc[i][2]+bias.z, acc[i][3]+bias.w);
        *(float4*)(g_value + (size_t)(pixbase + ty*4 + i)*64 + tx*4) = v;
    }
}

// ---------------------------------------------------------------------------
// Kernel 2: dw = depthwise3x3(inp)+bdw ; om = dw @ Wom[:, :108] + bom
// ---------------------------------------------------------------------------
__global__ __launch_bounds__(256) void k_offmask(const float* __restrict__ inp,
                                                 const float* __restrict__ Wdw,
                                                 const float* __restrict__ bdw,
                                                 const float* __restrict__ Wom,
                                                 const float* __restrict__ bom) {
    extern __shared__ float sm[];
    float* t_in  = sm;                 // [c][r][66]
    float* wdw_s = sm + 12672;         // [c][9]
    float* wom_s = sm + 12672 + 576;   // [k][112]

    int t  = blockIdx.x;
    int w0 = (t % TILES_X) * 64;
    int h  = (t / TILES_X) % Hn;
    int b  = t / (TILES_X * Hn);
    int tid = threadIdx.x;

    for (int i = tid; i < 576;  i += 256) wdw_s[i] = Wdw[i];
    for (int i = tid; i < 7168; i += 256) wom_s[i] = Wom[i];

    const float* src = inp + (size_t)b*Cn*HW;
    for (int i = tid; i < 64*3*66; i += 256) {
        int c   = i / 198;
        int rem = i - c*198;
        int r   = rem / 66;
        int pw  = rem - r*66;
        int hh  = h - 1 + r;
        int ww  = w0 - 1 + pw;
        float v = 0.f;
        if ((unsigned)hh < (unsigned)Hn && (unsigned)ww < (unsigned)Wn)
            v = src[(size_t)c*HW + (size_t)hh*Wn + ww];
        t_in[i] = v;
    }
    __syncthreads();

    float dwreg[16];
    #pragma unroll
    for (int ii = 0; ii < 16; ii++) {
        int item = tid + 256*ii;
        int c = item >> 6, p = item & 63;
        float a = __ldg(&bdw[c]);
        const float* ti = t_in + c*198;
        const float* wd = wdw_s + c*9;
        #pragma unroll
        for (int r = 0; r < 3; r++)
            #pragma unroll
            for (int kx = 0; kx < 3; kx++)
                a = fmaf(ti[r*66 + p + kx], wd[r*3 + kx], a);
        dwreg[ii] = a;
    }
    __syncthreads();
    float* dw_s = sm;         // reuse: [c][p]
    #pragma unroll
    for (int ii = 0; ii < 16; ii++)
        dw_s[tid + 256*ii] = dwreg[ii];
    __syncthreads();

    int ty = tid >> 4, tx = tid & 15;
    float acc[4][7];
    #pragma unroll
    for (int i = 0; i < 4; i++)
        #pragma unroll
        for (int j = 0; j < 7; j++) acc[i][j] = 0.f;

    const float4* d4 = (const float4*)dw_s;
    #pragma unroll
    for (int k = 0; k < 64; k++) {
        float4 a = d4[k*16 + ty];
        float av[4] = {a.x, a.y, a.z, a.w};
        float bw[7];
        #pragma unroll
        for (int jj = 0; jj < 7; jj++) bw[jj] = wom_s[k*112 + tx*7 + jj];
        #pragma unroll
        for (int i = 0; i < 4; i++)
            #pragma unroll
            for (int jj = 0; jj < 7; jj++)
                acc[i][jj] = fmaf(av[i], bw[jj], acc[i][jj]);
    }
    int pixbase = (b*Hn + h)*Wn + w0;
    #pragma unroll
    for (int i = 0; i < 4; i++) {
        float* dst = g_offmask + (size_t)(pixbase + ty*4 + i)*OMS;
        #pragma unroll
        for (int jj = 0; jj < 7; jj++) {
            int j = tx*7 + jj;
            if (j < OMS) dst[j] = acc[i][jj] + __ldg(&bom[j]);
        }
    }
}

// ---------------------------------------------------------------------------
// Kernel 3 (v2): 8x8 pixel tiles. Stage 12x12x64 value patch in smem,
// sample from smem (global fallback for out-of-patch corners), then Wo GEMM.
//
// smem floats: patch 9216 | om_s 6912 | wo_s 4096 | out_s 4096 = 24320 (97 KB)
// patch layout: float4 idx = c4*576 + pix*4 + g   (c4 in 0..3, pix 0..143, g 0..3)
//   -> LDS.128 banks = 16*(pix&1) + 4g : conflict-free for adjacent corners.
// ---------------------------------------------------------------------------
__global__ __launch_bounds__(256) void k_sample(const float* __restrict__ Wo,
                                                float* __restrict__ out) {
    extern __shared__ float sm[];
    float4* patch = (float4*)sm;                  // 2304 float4
    float*  om_s  = sm + 9216;                    // [p][108]
    float*  wo_s  = sm + 9216 + 6912;             // [k][c]
    float*  out_s = sm + 9216 + 6912 + 4096;      // [ch][p]

    int t   = blockIdx.x;
    int tx0 = (t % TXT) * TS;
    int ty0 = ((t / TXT) % TYT) * TS;
    int b   = t / (TXT * TYT);
    int tid = threadIdx.x;
    int row0 = ty0 - 2, col0 = tx0 - 2;

    for (int i = tid; i < 4096; i += 256) wo_s[i] = Wo[i];

    // stage om: 64 pixels x 27 float4
    {
        const float4* osrc = (const float4*)g_offmask;
        float4* odst = (float4*)om_s;
        for (int item = tid; item < 64*27; item += 256) {
            int p = item / 27, j = item - p*27;
            int gy = ty0 + (p >> 3), gx = tx0 + (p & 7);
            odst[p*27 + j] = osrc[((size_t)(b*HW) + (size_t)gy*Wn + gx)*27 + j];
        }
    }
    // stage value patch: 144 pixels x 16 float4 (zeros outside image)
    const float4* vsrc = (const float4*)(g_value + (size_t)b*HW*64);
    for (int item = tid; item < PPIX*16; item += 256) {
        int pix = item >> 4, q = item & 15;
        int py = pix / PATCH, pxl = pix - py*PATCH;
        int gy = row0 + py, gx = col0 + pxl;
        float4 v = make_float4(0.f, 0.f, 0.f, 0.f);
        if ((unsigned)gy < (unsigned)Hn && (unsigned)gx < (unsigned)Wn)
            v = vsrc[((size_t)gy*Wn + gx)*16 + q];
        patch[(q & 3)*(PPIX*4) + (pix << 2) + (q >> 2)] = v;
    }
    __syncthreads();

    // ---- phase 1: sampling. thread = (pixel p, group g), g fastest
    int g = tid & 3, p = tid >> 2;
    int pxi = tx0 + (p & 7);
    int pyi = ty0 + (p >> 3);
    const float* ob = om_s + p*OMS + g*27;

    float4 a0 = {0,0,0,0}, a1 = {0,0,0,0}, a2 = {0,0,0,0}, a3 = {0,0,0,0};
    const float4* vg = vsrc + g*4;   // group channel offset (g*16 floats)

    #pragma unroll
    for (int k = 0; k < 9; k++) {
        int ky = k / 3, kx = k - ky*3;
        float px = (float)(pxi + kx - 1) + ob[2*k];
        float py = (float)(pyi + ky - 1) + ob[2*k + 1];
        float m  = ob[18 + k];
        float x0f = floorf(px), y0f = floorf(py);
        float fx = px - x0f, fy = py - y0f;
        int x0 = (int)x0f, y0 = (int)y0f;
        #pragma unroll
        for (int dyc = 0; dyc < 2; dyc++) {
            #pragma unroll
            for (int dxc = 0; dxc < 2; dxc++) {
                int xi = x0 + dxc, yi = y0 + dyc;
                float wgt = m * (dyc ? fy : 1.f - fy) * (dxc ? fx : 1.f - fx);
                if ((unsigned)xi >= (unsigned)Wn || (unsigned)yi >= (unsigned)Hn)
                    wgt = 0.f;
                int lx = xi - col0, ly = yi - row0;
                float4 v0, v1, v2, v3;
                if ((unsigned)lx < PATCH && (unsigned)ly < PATCH) {
                    int base = ((ly*PATCH + lx) << 2) + g;
                    v0 = patch[base];
                    v1 = patch[base + PPIX*4];
                    v2 = patch[base + PPIX*8];
                    v3 = patch[base + PPIX*12];
                } else {
                    int xc = min(max(xi, 0), Wn - 1);
                    int yc = min(max(yi, 0), Hn - 1);
                    const float4* vp = vg + ((size_t)yc*Wn + xc)*16;
                    v0 = vp[0]; v1 = vp[1]; v2 = vp[2]; v3 = vp[3];
                }
                a0.x = fmaf(wgt, v0.x, a0.x); a0.y = fmaf(wgt, v0.y, a0.y);
                a0.z = fmaf(wgt, v0.z, a0.z); a0.w = fmaf(wgt, v0.w, a0.w);
                a1.x = fmaf(wgt, v1.x, a1.x); a1.y = fmaf(wgt, v1.y, a1.y);
                a1.z = fmaf(wgt, v1.z, a1.z); a1.w = fmaf(wgt, v1.w, a1.w);
                a2.x = fmaf(wgt, v2.x, a2.x); a2.y = fmaf(wgt, v2.y, a2.y);
                a2.z = fmaf(wgt, v2.z, a2.z); a2.w = fmaf(wgt, v2.w, a2.w);
                a3.x = fmaf(wgt, v3.x, a3.x); a3.y = fmaf(wgt, v3.y, a3.y);
                a3.z = fmaf(wgt, v3.z, a3.z); a3.w = fmaf(wgt, v3.w, a3.w);
            }
        }
    }
    {
        float accv[16] = {a0.x,a0.y,a0.z,a0.w, a1.x,a1.y,a1.z,a1.w,
                          a2.x,a2.y,a2.z,a2.w, a3.x,a3.y,a3.z,a3.w};
        #pragma unroll
        for (int cc = 0; cc < 16; cc++)
            out_s[(g*16 + cc)*64 + p] = accv[cc];
    }
    __syncthreads();

    // ---- phase 2: out2[c][p] = sum_k wo_s[k][c] * out_s[k][p], store NCHW
    int tyq = tid >> 4, txq = tid & 15;  // tyq -> channel group, txq -> pixel quad
    float q2[4][4];
    #pragma unroll
    for (int i = 0; i < 4; i++)
        #pragma unroll
        for (int j = 0; j < 4; j++) q2[i][j] = 0.f;

    const float4* W4 = (const float4*)wo_s;
    const float4* O4 = (const float4*)out_s;
    #pragma unroll
    for (int k = 0; k < 64; k++) {
        float4 a  = W4[k*16 + tyq];   // 4 channels
        float4 bb = O4[k*16 + txq];   // 4 pixels
        float av[4] = {a.x, a.y, a.z, a.w};
        float bw[4] = {bb.x, bb.y, bb.z, bb.w};
        #pragma unroll
        for (int i = 0; i < 4; i++)
            #pragma unroll
            for (int j = 0; j < 4; j++)
                q2[i][j] = fmaf(av[i], bw[j], q2[i][j]);
    }
    int orow = ty0 + (txq >> 1);
    int ocol = tx0 + (txq & 1)*4;
    #pragma unroll
    for (int i = 0; i < 4; i++) {
        int c = tyq*4 + i;
        float4 v = make_float4(q2[i][0], q2[i][1], q2[i][2], q2[i][3]);
        *(float4*)(out + ((size_t)(b*Cn + c)*Hn + orow)*Wn + ocol) = v;
    }
}

// ---------------------------------------------------------------------------
extern "C" void kernel_launch(void* const* d_in, const int* in_sizes, int n_in,
                              void* d_out, int out_size) {
    const float* inp = (const float*)d_in[0];
    const float* Wv  = (const float*)d_in[1];
    const float* bv  = (const float*)d_in[2];
    const float* Wdw = (const float*)d_in[3];
    const float* bdw = (const float*)d_in[4];
    const float* Wom = (const float*)d_in[5];
    const float* bom = (const float*)d_in[6];
    const float* Wo  = (const float*)d_in[7];
    float* out = (float*)d_out;

    const int smB = 20416 * 4;   // 81664 B
    const int smC = 24320 * 4;   // 97280 B
    cudaFuncSetAttribute(k_offmask, cudaFuncAttributeMaxDynamicSharedMemorySize, smB);
    cudaFuncSetAttribute(k_sample,  cudaFuncAttributeMaxDynamicSharedMemorySize, smC);

    k_value<<<NTILE, 256>>>(inp, Wv, bv);
    k_offmask<<<NTILE, 256, smB>>>(inp, Wdw, bdw, Wom, bom);
    k_sample<<<NTILE2, 256, smC>>>(Wo, out);
}